// round 13
// baseline (speedup 1.0000x reference)
#include <cuda_runtime.h>
#include <cuda_fp16.h>
#include <cstdint>

#define BN   2
#define SEQ  2048
#define DIM  1024
#define NH   16
#define DHD  64
#define NTOK (BN*SEQ)     // 4096
#define DFF  (4*DIM)      // 4096

// ---- scratch (device globals; no allocations allowed) ----
__device__ __half g_x_h [(size_t)NTOK*DIM];  // x converted to fp16
__device__ __half g_q [(size_t)NTOK*DIM];    // [B,H,S,DH] fp16, pre-scaled by log2e/8
__device__ __half g_k [(size_t)NTOK*DIM];
__device__ __half g_v [(size_t)NTOK*DIM];
__device__ float g_att[(size_t)NTOK*DIM];    // [B,S,D]
__device__ float g_h1 [(size_t)NTOK*DIM];
__device__ __half g_h1_h[(size_t)NTOK*DIM];  // fp16 copy of h1 for FFN1
__device__ __half g_act_h[(size_t)NTOK*DFF]; // relu(h1 W1 + b1) fp16
__device__ float g_ffn[(size_t)NTOK*DIM];

// pre-transposed fp16 weights, [N][K] K-major (= B^T row-major)
__device__ __half g_qkv_h[(size_t)3*DIM*DIM];   // [3072][1024]
__device__ __half g_w1_h [(size_t)DFF*DIM];     // [4096][1024]
__device__ __half g_w2_h [(size_t)DIM*DFF];     // [1024][4096]

// ================= helpers (baseline sm_80+ features only) =================
__device__ __forceinline__ uint32_t smem_u32(const void* p) {
    uint32_t a;
    asm("{ .reg .u64 t; cvta.to.shared.u64 t, %1; cvt.u32.u64 %0, t; }" : "=r"(a) : "l"(p));
    return a;
}
__device__ __forceinline__ void ldsm4(uint32_t* r, uint32_t addr) {
    asm volatile("ldmatrix.sync.aligned.m8n8.x4.shared.b16 {%0,%1,%2,%3}, [%4];"
        : "=r"(r[0]), "=r"(r[1]), "=r"(r[2]), "=r"(r[3]) : "r"(addr));
}
__device__ __forceinline__ void ldsm4t(uint32_t* r, uint32_t addr) {
    asm volatile("ldmatrix.sync.aligned.m8n8.x4.trans.shared.b16 {%0,%1,%2,%3}, [%4];"
        : "=r"(r[0]), "=r"(r[1]), "=r"(r[2]), "=r"(r[3]) : "r"(addr));
}
__device__ __forceinline__ void mma_f16(float* c, const uint32_t* a, const uint32_t* b) {
    asm volatile("mma.sync.aligned.m16n8k16.row.col.f32.f16.f16.f32 "
        "{%0,%1,%2,%3}, {%4,%5,%6,%7}, {%8,%9}, {%0,%1,%2,%3};"
        : "+f"(c[0]), "+f"(c[1]), "+f"(c[2]), "+f"(c[3])
        : "r"(a[0]), "r"(a[1]), "r"(a[2]), "r"(a[3]), "r"(b[0]), "r"(b[1]));
}
__device__ __forceinline__ uint32_t pack_h2(float x, float y) {
    __half2 h = __floats2half2_rn(x, y);
    return *(uint32_t*)&h;
}
#define CP_ASYNC16(dst, src) \
    asm volatile("cp.async.cg.shared.global [%0], [%1], 16;" :: "r"(dst), "l"(src))
#define CP_COMMIT() asm volatile("cp.async.commit_group;" ::: "memory")
#define CP_WAIT(n)  asm volatile("cp.async.wait_group %0;" :: "n"(n) : "memory")

// ================= preprocess kernels =================
__global__ __launch_bounds__(256)
void transpose_h_kernel(const float* __restrict__ src, __half* __restrict__ dst,
                        int R, int C, size_t sStride, size_t dStride)
{
    __shared__ float t[32][33];
    const int bx = blockIdx.x * 32;
    const int by = blockIdx.y * 32;
    src += (size_t)blockIdx.z * sStride;
    dst += (size_t)blockIdx.z * dStride;
    const int x = threadIdx.x & 31;
    const int y0 = threadIdx.x >> 5;
#pragma unroll
    for (int j = 0; j < 32; j += 8)
        t[y0 + j][x] = src[(size_t)(by + y0 + j) * C + bx + x];
    __syncthreads();
#pragma unroll
    for (int j = 0; j < 32; j += 8)
        dst[(size_t)(bx + y0 + j) * R + by + x] = __float2half_rn(t[x][y0 + j]);
}

__global__ __launch_bounds__(256)
void transpose_qkv_kernel(const float* __restrict__ Wq, const float* __restrict__ Wk,
                          const float* __restrict__ Wv, __half* __restrict__ dst)
{
    __shared__ float t[32][33];
    const int which = blockIdx.z >> 4;
    const int head  = blockIdx.z & 15;
    const float* src = ((which == 0) ? Wq : (which == 1) ? Wk : Wv)
                     + (size_t)head * DIM * DHD;
    __half* d = dst + (size_t)which * DIM * DIM + (size_t)head * DHD * DIM;
    const int bx = blockIdx.x * 32;
    const int by = blockIdx.y * 32;
    const int x = threadIdx.x & 31;
    const int y0 = threadIdx.x >> 5;
#pragma unroll
    for (int j = 0; j < 32; j += 8)
        t[y0 + j][x] = src[(size_t)(by + y0 + j) * DHD + bx + x];
    __syncthreads();
#pragma unroll
    for (int j = 0; j < 32; j += 8)
        d[(size_t)(bx + y0 + j) * DIM + by + x] = __float2half_rn(t[x][y0 + j]);
}

__global__ __launch_bounds__(256)
void f2h_kernel(const float* __restrict__ src, __half* __restrict__ dst)
{
    size_t i = ((size_t)blockIdx.x * 256 + threadIdx.x) * 8;
    float4 a = *(const float4*)(src + i);
    float4 b = *(const float4*)(src + i + 4);
    uint32_t* d = (uint32_t*)(dst + i);
    d[0] = pack_h2(a.x, a.y);
    d[1] = pack_h2(a.z, a.w);
    d[2] = pack_h2(b.x, b.y);
    d[3] = pack_h2(b.z, b.w);
}

// ================= HMMA fp16 GEMM (4-stage cp.async, 32-wide chunks) =========
// C = A[M,K](fp16) * B^T[N,K](fp16), tile 128x128, 8 warps, K-chunk 32, 4 stages.
// Per chunk: wait(2) -> sync -> prefetch(i+3) -> compute(i). One barrier/chunk.
// MODE 0: QKV -> fp16 H0/H1/H2 (q scaled by log2e/8), scatter [B,H,S,DH]
// MODE 1: bias + ReLU -> fp16 H0   MODE 2: bias -> fp32 C0
#define KC3 32
#define AST3 40                                  // 80B row stride: conflict-free ldsm
#define GSTG3 (128 * AST3)                       // elems per matrix per stage
#define STAGE3_B (2 * GSTG3 * 2)                 // bytes per stage (A+B) = 20480
#define GEMM_SMEM (4 * STAGE3_B)                 // 81920 B -> 2 CTAs/SM

template<int MODE>
__global__ __launch_bounds__(256, 2)
void gemm_mma(const __half* __restrict__ A,
              const __half* __restrict__ BH,
              const float* __restrict__ b0, const float* __restrict__ b1,
              const float* __restrict__ b2,
              float* __restrict__ C0,
              __half* __restrict__ H0, __half* __restrict__ H1, __half* __restrict__ H2,
              int K, int N)
{
    extern __shared__ __align__(16) __half gsm[];
    const uint32_t smb = smem_u32(gsm);

    const int tid = threadIdx.x;
    const int wid = tid >> 5, lane = tid & 31;
    const int wm = wid & 3;
    const int wn = wid >> 2;
    const int m0 = blockIdx.x * 128, n0 = blockIdx.y * 128;

    const __half* Ap = A + (size_t)m0 * K;
    const __half* Bp = BH + (size_t)n0 * K;

    const uint32_t aIdx = (uint32_t)((wm * 32 + (lane & 15)) * AST3 + ((lane & 16) ? 8 : 0));
    const uint32_t bIdx = (uint32_t)((wn * 64 + (lane & 7) + ((lane & 16) ? 8 : 0)) * AST3
                                     + ((lane & 8) ? 8 : 0));
    // per-thread staging coords: 512 16B-chunks per matrix, 2 per thread
    const int pr0 = tid >> 2;            // row for i=0 (0..63)
    const int pr1 = (tid + 256) >> 2;    // row for i=1 (64..127)
    const int pc  = (tid & 3) * 8;       // col in fp16 elems

    float acc[2][8][4];
#pragma unroll
    for (int i = 0; i < 2; i++)
#pragma unroll
        for (int j = 0; j < 8; j++)
#pragma unroll
            for (int q = 0; q < 4; q++) acc[i][j][q] = 0.f;

    const int NCk = K >> 5;

    // prologue: prefetch chunks 0..2 into stages 0..2 (one commit each)
#pragma unroll
    for (int s = 0; s < 3; s++) {
        uint32_t sA = smb + (uint32_t)s * STAGE3_B;
        uint32_t sB = sA + GSTG3 * 2;
        int k0 = s * KC3;
        CP_ASYNC16(sA + (uint32_t)(pr0 * AST3 + pc) * 2, Ap + (size_t)pr0 * K + k0 + pc);
        CP_ASYNC16(sA + (uint32_t)(pr1 * AST3 + pc) * 2, Ap + (size_t)pr1 * K + k0 + pc);
        CP_ASYNC16(sB + (uint32_t)(pr0 * AST3 + pc) * 2, Bp + (size_t)pr0 * K + k0 + pc);
        CP_ASYNC16(sB + (uint32_t)(pr1 * AST3 + pc) * 2, Bp + (size_t)pr1 * K + k0 + pc);
        CP_COMMIT();
    }

    for (int cch = 0; cch < NCk; cch++) {
        CP_WAIT(2);            // chunk cch complete (newest 2 groups may be in flight)
        __syncthreads();       // all threads done computing chunk cch-1
        if (cch + 3 < NCk) {   // prefetch chunk cch+3 into stage (cch+3)&3 (= stage of cch-1)
            int k0 = (cch + 3) * KC3;
            uint32_t sA = smb + (uint32_t)((cch + 3) & 3) * STAGE3_B;
            uint32_t sB = sA + GSTG3 * 2;
            CP_ASYNC16(sA + (uint32_t)(pr0 * AST3 + pc) * 2, Ap + (size_t)pr0 * K + k0 + pc);
            CP_ASYNC16(sA + (uint32_t)(pr1 * AST3 + pc) * 2, Ap + (size_t)pr1 * K + k0 + pc);
            CP_ASYNC16(sB + (uint32_t)(pr0 * AST3 + pc) * 2, Bp + (size_t)pr0 * K + k0 + pc);
            CP_ASYNC16(sB + (uint32_t)(pr1 * AST3 + pc) * 2, Bp + (size_t)pr1 * K + k0 + pc);
        }
        CP_COMMIT();           // always commit -> uniform group accounting

        uint32_t sA = smb + (uint32_t)((cch & 3)) * STAGE3_B;
        uint32_t sB = sA + GSTG3 * 2;
#pragma unroll
        for (int ks = 0; ks < 2; ks++) {
            uint32_t ah[2][4];
#pragma unroll
            for (int mi = 0; mi < 2; mi++)
                ldsm4(ah[mi], sA + (aIdx + mi * 16 * AST3 + ks * 16) * 2);
#pragma unroll
            for (int njg = 0; njg < 4; njg++) {
                uint32_t bh4[4];
                ldsm4(bh4, sB + (bIdx + njg * 16 * AST3 + ks * 16) * 2);
#pragma unroll
                for (int mi = 0; mi < 2; mi++) {
                    mma_f16(acc[mi][njg * 2 + 0], ah[mi], bh4 + 0);
                    mma_f16(acc[mi][njg * 2 + 1], ah[mi], bh4 + 2);
                }
            }
        }
    }

    // ---- epilogue ----
    const int g = lane >> 2, tig = lane & 3;
#pragma unroll
    for (int mi = 0; mi < 2; mi++) {
#pragma unroll
        for (int nj = 0; nj < 8; nj++) {
            int ctile = wn * 64 + nj * 8 + tig * 2;
#pragma unroll
            for (int half = 0; half < 2; half++) {
                int m = m0 + wm * 32 + mi * 16 + g + half * 8;
                float v0 = acc[mi][nj][half * 2 + 0];
                float v1 = acc[mi][nj][half * 2 + 1];
                if (MODE == 0) {
                    int which = n0 >> 10;
                    const float* bsel = (which == 0) ? b0 : ((which == 1) ? b1 : b2);
                    __half* Hsel = (which == 0) ? H0 : ((which == 1) ? H1 : H2);
                    float scale = (which == 0) ? 0.125f * 1.44269504f : 1.0f;
                    int nloc = (n0 & 1023) + ctile;
                    int h = nloc >> 6, e = nloc & 63;
                    int bb = m >> 11, s = m & 2047;
                    __half2 w = __floats2half2_rn((v0 + bsel[nloc]) * scale,
                                                  (v1 + bsel[nloc + 1]) * scale);
                    *(__half2*)(Hsel + (((size_t)bb * NH + h) * SEQ + s) * DHD + e) = w;
                } else if (MODE == 1) {
                    int n = n0 + ctile;
                    __half2 w = __floats2half2_rn(fmaxf(v0 + b0[n], 0.f),
                                                  fmaxf(v1 + b0[n + 1], 0.f));
                    *(__half2*)(H0 + (size_t)m * N + n) = w;
                } else {
                    int n = n0 + ctile;
                    float2 w = make_float2(v0 + b0[n], v1 + b0[n + 1]);
                    *(float2*)(C0 + (size_t)m * N + n) = w;
                }
            }
        }
    }
}

// ================= HMMA fp16 flash attention (single-sync pipeline) =====
#define ATS2 72
#define Q_ELEMS (128*ATS2)
#define STG_ELEMS (64*ATS2)
#define ATT_SMEM_BYTES ((Q_ELEMS + 4*STG_ELEMS) * 2)

__global__ __launch_bounds__(256, 2)
void attn_mma_kernel(const __half* __restrict__ Q, const __half* __restrict__ Kg,
                     const __half* __restrict__ Vg, float* __restrict__ O)
{
    extern __shared__ __align__(16) __half smh[];
    __half* Qh = smh;

    const int tid = threadIdx.x;
    const int wid = tid >> 5, lane = tid & 31;
    const int g = lane >> 2, t = lane & 3;
    const int b = blockIdx.z, h = blockIdx.y;
    const int q0 = blockIdx.x * 128;
    const size_t bh = ((size_t)b * NH + h) * SEQ;
    const __half* qb = Q + (bh + q0) * DHD;

    const uint32_t sQ  = smem_u32(Qh);
    const uint32_t sSt = sQ + Q_ELEMS * 2;

    // prologue: Q + tile 0 in one group
#pragma unroll
    for (int i = 0; i < 4; i++) {
        int idx = tid + i * 256;
        int r = idx >> 3, c = idx & 7;
        CP_ASYNC16(sQ + (uint32_t)(r * ATS2 + c * 8) * 2, qb + r * DHD + c * 8);
    }
    {
        const __half* kb = Kg + bh * DHD;
        const __half* vb = Vg + bh * DHD;
#pragma unroll
        for (int i = 0; i < 2; i++) {
            int idx = tid + i * 256;
            int r = idx >> 3, c = idx & 7;
            uint32_t d = (uint32_t)(r * ATS2 + c * 8) * 2;
            CP_ASYNC16(sSt + d, kb + r * DHD + c * 8);
            CP_ASYNC16(sSt + STG_ELEMS * 2 + d, vb + r * DHD + c * 8);
        }
    }
    CP_COMMIT();

    const uint32_t aIdx = (uint32_t)((wid * 16 + (lane & 15)) * ATS2 + ((lane & 16) ? 8 : 0));
    const uint32_t kIdx = (uint32_t)(((lane & 7) + ((lane & 16) ? 8 : 0)) * ATS2
                                     + ((lane & 8) ? 8 : 0));
    const uint32_t vIdx = (uint32_t)((lane & 15) * ATS2 + ((lane & 16) ? 8 : 0));

    uint32_t qf[4][4];
    float o[8][4];
    float l0p = 0.f, l1p = 0.f;
#pragma unroll
    for (int j = 0; j < 8; j++)
#pragma unroll
        for (int q = 0; q < 4; q++) o[j][q] = 0.f;

    const int NT = SEQ / 64;
    for (int kt = 0; kt < NT; kt++) {
        CP_WAIT(0);
        __syncthreads();
        if (kt + 1 < NT) {   // prefetch next tile into other stage (post-barrier: safe)
            const __half* kb = Kg + (bh + (size_t)(kt + 1) * 64) * DHD;
            const __half* vb = Vg + (bh + (size_t)(kt + 1) * 64) * DHD;
            uint32_t base = sSt + (uint32_t)(((kt + 1) & 1) * 2 * STG_ELEMS) * 2;
#pragma unroll
            for (int i = 0; i < 2; i++) {
                int idx = tid + i * 256;
                int r = idx >> 3, c = idx & 7;
                uint32_t d = (uint32_t)(r * ATS2 + c * 8) * 2;
                CP_ASYNC16(base + d, kb + r * DHD + c * 8);
                CP_ASYNC16(base + STG_ELEMS * 2 + d, vb + r * DHD + c * 8);
            }
            CP_COMMIT();
        }
        if (kt == 0) {
#pragma unroll
            for (int ks = 0; ks < 4; ks++)
                ldsm4(qf[ks], sQ + (aIdx + ks * 16) * 2);
        }
        const uint32_t sK = sSt + (uint32_t)((kt & 1) * 2 * STG_ELEMS) * 2;
        const uint32_t sV = sK + STG_ELEMS * 2;

        float sc[8][4];
#pragma unroll
        for (int j = 0; j < 8; j++)
#pragma unroll
            for (int q = 0; q < 4; q++) sc[j][q] = 0.f;
#pragma unroll
        for (int ks = 0; ks < 4; ks++) {
#pragma unroll
            for (int njg = 0; njg < 4; njg++) {
                uint32_t bh4[4];
                ldsm4(bh4, sK + (kIdx + njg * 16 * ATS2 + ks * 16) * 2);
                mma_f16(sc[njg * 2 + 0], qf[ks], bh4 + 0);
                mma_f16(sc[njg * 2 + 1], qf[ks], bh4 + 2);
            }
        }

        uint32_t pf[4][4];
#pragma unroll
        for (int ks = 0; ks < 4; ks++) {
            pf[ks][0] = pack_h2(sc[2 * ks][0],     sc[2 * ks][1]);
            pf[ks][1] = pack_h2(sc[2 * ks][2],     sc[2 * ks][3]);
            pf[ks][2] = pack_h2(sc[2 * ks + 1][0], sc[2 * ks + 1][1]);
            pf[ks][3] = pack_h2(sc[2 * ks + 1][2], sc[2 * ks + 1][3]);
#pragma unroll
            for (int i = 0; i < 4; i++)
                asm("ex2.approx.f16x2 %0, %0;" : "+r"(pf[ks][i]));
        }

        {
            __half2 a0 = __float2half2_rn(0.f), a1 = a0;
#pragma unroll
            for (int ks = 0; ks < 4; ks++) {
                a0 = __hadd2(a0, *(__half2*)&pf[ks][0]);
                a0 = __hadd2(a0, *(__half2*)&pf[ks][2]);
                a1 = __hadd2(a1, *(__half2*)&pf[ks][1]);
                a1 = __hadd2(a1, *(__half2*)&pf[ks][3]);
            }
            float2 f0 = __half22float2(a0), f1 = __half22float2(a1);
            l0p += f0.x + f0.y;
            l1p += f1.x + f1.y;
        }

#pragma unroll
        for (int ks = 0; ks < 4; ks++) {
#pragma unroll
            for (int njg = 0; njg < 4; njg++) {
                uint32_t vv[4];
                ldsm4t(vv, sV + (vIdx + ks * 16 * ATS2 + njg * 16) * 2);
                mma_f16(o[njg * 2 + 0], pf[ks], vv + 0);
                mma_f16(o[njg * 2 + 1], pf[ks], vv + 2);
            }
        }
    }

    l0p += __shfl_xor_sync(0xffffffffu, l0p, 1);
    l0p += __shfl_xor_sync(0xffffffffu, l0p, 2);
    l1p += __shfl_xor_sync(0xffffffffu, l1p, 1);
    l1p += __shfl_xor_sync(0xffffffffu, l1p, 2);
    float inv0 = 1.f / l0p, inv1 = 1.f / l1p;
    int row0 = q0 + wid * 16 + g;
#pragma unroll
    for (int j = 0; j < 8; j++) {
        int e = j * 8 + t * 2;
        float* dst0 = O + ((size_t)b * SEQ + row0) * DIM + h * DHD + e;
        float* dst1 = O + ((size_t)b * SEQ + row0 + 8) * DIM + h * DHD + e;
        *(float2*)dst0 = make_float2(o[j][0] * inv0, o[j][1] * inv0);
        *(float2*)dst1 = make_float2(o[j][2] * inv1, o[j][3] * inv1);
    }
}

// ================= add + layernorm (optional fp16 secondary output) ==========
__global__ __launch_bounds__(256)
void add_ln_kernel(const float* __restrict__ a, const float* __restrict__ r,
                   const float* __restrict__ gg, const float* __restrict__ bb,
                   float* __restrict__ out, __half* __restrict__ outh)
{
    const int row = blockIdx.x;
    const size_t base = (size_t)row * DIM;
    float v[4];
    float sum = 0.f, sq = 0.f;
#pragma unroll
    for (int k = 0; k < 4; k++) {
        int i = threadIdx.x + k * 256;
        float tv = a[base + i] + r[base + i];
        v[k] = tv;
        sum += tv;
        sq  += tv * tv;
    }
#pragma unroll
    for (int off = 16; off; off >>= 1) {
        sum += __shfl_xor_sync(0xffffffffu, sum, off);
        sq  += __shfl_xor_sync(0xffffffffu, sq,  off);
    }
    __shared__ float s1[8], s2[8];
    int w = threadIdx.x >> 5, ln = threadIdx.x & 31;
    if (ln == 0) { s1[w] = sum; s2[w] = sq; }
    __syncthreads();
    if (threadIdx.x == 0) {
        float ts = 0.f, tq = 0.f;
#pragma unroll
        for (int i = 0; i < 8; i++) { ts += s1[i]; tq += s2[i]; }
        s1[0] = ts; s2[0] = tq;
    }
    __syncthreads();
    float mean = s1[0] * (1.f / DIM);
    float var  = s2[0] * (1.f / DIM) - mean * mean;
    float rstd = rsqrtf(var + 1e-5f);
#pragma unroll
    for (int k = 0; k < 4; k++) {
        int i = threadIdx.x + k * 256;
        float y = (v[k] - mean) * rstd * gg[i] + bb[i];
        out[base + i] = y;
        if (outh) outh[base + i] = __float2half_rn(y);
    }
}

// ================= launch =================
extern "C" void kernel_launch(void* const* d_in, const int* in_sizes, int n_in,
                              void* d_out, int out_size)
{
    (void)in_sizes; (void)n_in; (void)out_size;
    const float* x  = (const float*)d_in[0];
    const float* Wq = (const float*)d_in[2];
    const float* bq = (const float*)d_in[3];
    const float* Wk = (const float*)d_in[4];
    const float* bk = (const float*)d_in[5];
    const float* Wv = (const float*)d_in[6];
    const float* bv = (const float*)d_in[7];
    const float* lg = (const float*)d_in[8];
    const float* lb = (const float*)d_in[9];
    const float* W1 = (const float*)d_in[10];
    const float* b1 = (const float*)d_in[11];
    const float* W2 = (const float*)d_in[12];
    const float* b2 = (const float*)d_in[13];
    float* out = (float*)d_out;

    float *attp, *h1p, *ffnp;
    __half *xh, *qp, *kp, *vp, *h1h, *acth;
    cudaGetSymbolAddress((void**)&xh,   g_x_h);
    cudaGetSymbolAddress((void**)&qp,   g_q);
    cudaGetSymbolAddress((void**)&kp,   g_k);
    cudaGetSymbolAddress((void**)&vp,   g_v);
    cudaGetSymbolAddress((void**)&attp, g_att);
    cudaGetSymbolAddress((void**)&h1p,  g_h1);
    cudaGetSymbolAddress((void**)&h1h,  g_h1_h);
    cudaGetSymbolAddress((void**)&acth, g_act_h);
    cudaGetSymbolAddress((void**)&ffnp, g_ffn);

    __half *qkvh, *w1h, *w2h;
    cudaGetSymbolAddress((void**)&qkvh, g_qkv_h);
    cudaGetSymbolAddress((void**)&w1h,  g_w1_h);
    cudaGetSymbolAddress((void**)&w2h,  g_w2_h);

    cudaFuncSetAttribute(attn_mma_kernel,
                         cudaFuncAttributeMaxDynamicSharedMemorySize, ATT_SMEM_BYTES);
    cudaFuncSetAttribute(gemm_mma<0>,
                         cudaFuncAttributeMaxDynamicSharedMemorySize, GEMM_SMEM);
    cudaFuncSetAttribute(gemm_mma<1>,
                         cudaFuncAttributeMaxDynamicSharedMemorySize, GEMM_SMEM);
    cudaFuncSetAttribute(gemm_mma<2>,
                         cudaFuncAttributeMaxDynamicSharedMemorySize, GEMM_SMEM);

    dim3 blk(256);

    // 0) preprocess: weights -> fp16 transposed; x -> fp16
    transpose_qkv_kernel<<<dim3(2, 32, 48), blk>>>(Wq, Wk, Wv, qkvh);
    transpose_h_kernel<<<dim3(128, 32, 1), blk>>>(W1, w1h, DIM, DFF, 0, 0);
    transpose_h_kernel<<<dim3(32, 128, 1), blk>>>(W2, w2h, DFF, DIM, 0, 0);
    f2h_kernel<<<(NTOK * DIM) / (256 * 8), blk>>>(x, xh);

    // 1) fused QKV projection -> fp16 q(scaled)/k/v
    gemm_mma<0><<<dim3(NTOK / 128, (3 * DIM) / 128), blk, GEMM_SMEM>>>(
        xh, qkvh, bq, bk, bv, nullptr, qp, kp, vp, DIM, 3 * DIM);

    // 2) flash attention -> g_att [B,S,D]
    attn_mma_kernel<<<dim3(SEQ / 128, NH, BN), blk, ATT_SMEM_BYTES>>>(qp, kp, vp, attp);

    // 3) h1 = LN(x + mha), fp32 + fp16 copies
    add_ln_kernel<<<NTOK, blk>>>(x, attp, lg, lb, h1p, h1h);

    // 4) act = relu(h1 @ W1 + b1) -> fp16
    gemm_mma<1><<<dim3(NTOK / 128, DFF / 128), blk, GEMM_SMEM>>>(
        h1h, w1h, b1, nullptr, nullptr, nullptr, acth, nullptr, nullptr, DIM, DFF);

    // 5) ffn = act @ W2 + b2 -> fp32
    gemm_mma<2><<<dim3(NTOK / 128, DIM / 128), blk, GEMM_SMEM>>>(
        acth, w2h, b2, nullptr, nullptr, ffnp, nullptr, nullptr, nullptr, DFF, DIM);

    // 6) out = LN(h1 + ffn)
    add_ln_kernel<<<NTOK, blk>>>(h1p, ffnp, lg, lb, out, nullptr);
}

// round 14
// speedup vs baseline: 1.0232x; 1.0232x over previous
#include <cuda_runtime.h>
#include <cuda_fp16.h>
#include <cstdint>

#define BN   2
#define SEQ  2048
#define DIM  1024
#define NH   16
#define DHD  64
#define NTOK (BN*SEQ)     // 4096
#define DFF  (4*DIM)      // 4096

// ---- scratch (device globals; no allocations allowed) ----
__device__ __half g_x_h [(size_t)NTOK*DIM];  // x converted to fp16
__device__ __half g_q [(size_t)NTOK*DIM];    // [B,H,S,DH] fp16, pre-scaled by log2e/8
__device__ __half g_k [(size_t)NTOK*DIM];
__device__ __half g_v [(size_t)NTOK*DIM];
__device__ float g_att[(size_t)NTOK*DIM];    // [B,S,D]
__device__ float g_h1 [(size_t)NTOK*DIM];
__device__ __half g_h1_h[(size_t)NTOK*DIM];  // fp16 copy of h1 for FFN1
__device__ __half g_act_h[(size_t)NTOK*DFF]; // relu(h1 W1 + b1) fp16
__device__ float g_res[(size_t)NTOK*DIM];    // h1 + ffn (fused in FFN2 epilogue)

// pre-transposed fp16 weights, [N][K] K-major (= B^T row-major)
__device__ __half g_qkv_h[(size_t)3*DIM*DIM];   // [3072][1024]
__device__ __half g_w1_h [(size_t)DFF*DIM];     // [4096][1024]
__device__ __half g_w2_h [(size_t)DIM*DFF];     // [1024][4096]

// ================= helpers (baseline sm_80+ features only) =================
__device__ __forceinline__ uint32_t smem_u32(const void* p) {
    uint32_t a;
    asm("{ .reg .u64 t; cvta.to.shared.u64 t, %1; cvt.u32.u64 %0, t; }" : "=r"(a) : "l"(p));
    return a;
}
__device__ __forceinline__ void ldsm4(uint32_t* r, uint32_t addr) {
    asm volatile("ldmatrix.sync.aligned.m8n8.x4.shared.b16 {%0,%1,%2,%3}, [%4];"
        : "=r"(r[0]), "=r"(r[1]), "=r"(r[2]), "=r"(r[3]) : "r"(addr));
}
__device__ __forceinline__ void ldsm4t(uint32_t* r, uint32_t addr) {
    asm volatile("ldmatrix.sync.aligned.m8n8.x4.trans.shared.b16 {%0,%1,%2,%3}, [%4];"
        : "=r"(r[0]), "=r"(r[1]), "=r"(r[2]), "=r"(r[3]) : "r"(addr));
}
__device__ __forceinline__ void mma_f16(float* c, const uint32_t* a, const uint32_t* b) {
    asm volatile("mma.sync.aligned.m16n8k16.row.col.f32.f16.f16.f32 "
        "{%0,%1,%2,%3}, {%4,%5,%6,%7}, {%8,%9}, {%0,%1,%2,%3};"
        : "+f"(c[0]), "+f"(c[1]), "+f"(c[2]), "+f"(c[3])
        : "r"(a[0]), "r"(a[1]), "r"(a[2]), "r"(a[3]), "r"(b[0]), "r"(b[1]));
}
__device__ __forceinline__ uint32_t pack_h2(float x, float y) {
    __half2 h = __floats2half2_rn(x, y);
    return *(uint32_t*)&h;
}
#define CP_ASYNC16(dst, src) \
    asm volatile("cp.async.cg.shared.global [%0], [%1], 16;" :: "r"(dst), "l"(src))
#define CP_COMMIT() asm volatile("cp.async.commit_group;" ::: "memory")
#define CP_WAIT(n)  asm volatile("cp.async.wait_group %0;" :: "n"(n) : "memory")

// ================= preprocess kernels =================
__global__ __launch_bounds__(256)
void transpose_h_kernel(const float* __restrict__ src, __half* __restrict__ dst,
                        int R, int C, size_t sStride, size_t dStride)
{
    __shared__ float t[32][33];
    const int bx = blockIdx.x * 32;
    const int by = blockIdx.y * 32;
    src += (size_t)blockIdx.z * sStride;
    dst += (size_t)blockIdx.z * dStride;
    const int x = threadIdx.x & 31;
    const int y0 = threadIdx.x >> 5;
#pragma unroll
    for (int j = 0; j < 32; j += 8)
        t[y0 + j][x] = src[(size_t)(by + y0 + j) * C + bx + x];
    __syncthreads();
#pragma unroll
    for (int j = 0; j < 32; j += 8)
        dst[(size_t)(bx + y0 + j) * R + by + x] = __float2half_rn(t[x][y0 + j]);
}

__global__ __launch_bounds__(256)
void transpose_qkv_kernel(const float* __restrict__ Wq, const float* __restrict__ Wk,
                          const float* __restrict__ Wv, __half* __restrict__ dst)
{
    __shared__ float t[32][33];
    const int which = blockIdx.z >> 4;
    const int head  = blockIdx.z & 15;
    const float* src = ((which == 0) ? Wq : (which == 1) ? Wk : Wv)
                     + (size_t)head * DIM * DHD;
    __half* d = dst + (size_t)which * DIM * DIM + (size_t)head * DHD * DIM;
    const int bx = blockIdx.x * 32;
    const int by = blockIdx.y * 32;
    const int x = threadIdx.x & 31;
    const int y0 = threadIdx.x >> 5;
#pragma unroll
    for (int j = 0; j < 32; j += 8)
        t[y0 + j][x] = src[(size_t)(by + y0 + j) * DHD + bx + x];
    __syncthreads();
#pragma unroll
    for (int j = 0; j < 32; j += 8)
        d[(size_t)(bx + y0 + j) * DIM + by + x] = __float2half_rn(t[x][y0 + j]);
}

__global__ __launch_bounds__(256)
void f2h_kernel(const float* __restrict__ src, __half* __restrict__ dst)
{
    size_t i = ((size_t)blockIdx.x * 256 + threadIdx.x) * 8;
    float4 a = *(const float4*)(src + i);
    float4 b = *(const float4*)(src + i + 4);
    uint32_t* d = (uint32_t*)(dst + i);
    d[0] = pack_h2(a.x, a.y);
    d[1] = pack_h2(a.z, a.w);
    d[2] = pack_h2(b.x, b.y);
    d[3] = pack_h2(b.z, b.w);
}

// ================= HMMA fp16 GEMM (2-stage cp.async, single sync/chunk) ======
// C = A[M,K](fp16) * B^T[N,K](fp16), tile 128x128, 8 warps, K-chunk 64.
// Per chunk: wait(0) -> sync -> prefetch(i+1, into stage sync just freed) -> compute(i).
// MODE 0: QKV -> fp16 H0/H1/H2 (q scaled by log2e/8), scatter [B,H,S,DH]
// MODE 1: bias + ReLU -> fp16 H0
// MODE 2: bias + residual R0 -> fp32 C0 (C0 = acc + bias + R0)
#define AST 72
#define GSTG (128 * AST)                  // elems per matrix per stage
#define GEMM_SMEM (4 * GSTG * 2)          // 2 stages x (A,B) = 73728 B

template<int MODE>
__global__ __launch_bounds__(256, 2)
void gemm_mma(const __half* __restrict__ A,
              const __half* __restrict__ BH,
              const float* __restrict__ b0, const float* __restrict__ b1,
              const float* __restrict__ b2,
              float* __restrict__ C0, const float* __restrict__ R0,
              __half* __restrict__ H0, __half* __restrict__ H1, __half* __restrict__ H2,
              int K, int N)
{
    extern __shared__ __align__(16) __half gsm[];
    const uint32_t smb = smem_u32(gsm);

    const int tid = threadIdx.x;
    const int wid = tid >> 5, lane = tid & 31;
    const int wm = wid & 3;
    const int wn = wid >> 2;
    const int m0 = blockIdx.x * 128, n0 = blockIdx.y * 128;

    const __half* Ap = A + (size_t)m0 * K;
    const __half* Bp = BH + (size_t)n0 * K;

    const uint32_t aIdx = (uint32_t)((wm * 32 + (lane & 15)) * AST + ((lane & 16) ? 8 : 0));
    const uint32_t bIdx = (uint32_t)((wn * 64 + (lane & 7) + ((lane & 16) ? 8 : 0)) * AST
                                     + ((lane & 8) ? 8 : 0));

    float acc[2][8][4];
#pragma unroll
    for (int i = 0; i < 2; i++)
#pragma unroll
        for (int j = 0; j < 8; j++)
#pragma unroll
            for (int q = 0; q < 4; q++) acc[i][j][q] = 0.f;

    const int NCk = K >> 6;

    // prologue: prefetch chunk 0 into stage 0
    {
        uint32_t sA = smb, sB = smb + GSTG * 2;
#pragma unroll
        for (int i = 0; i < 4; i++) {
            int idx = tid + i * 256;
            int r = idx >> 3, c = idx & 7;
            uint32_t d = (uint32_t)(r * AST + c * 8) * 2;
            CP_ASYNC16(sA + d, Ap + (size_t)r * K + c * 8);
            CP_ASYNC16(sB + d, Bp + (size_t)r * K + c * 8);
        }
    }
    CP_COMMIT();

    for (int cch = 0; cch < NCk; cch++) {
        CP_WAIT(0);        // chunk cch loads complete (no newer groups committed yet)
        __syncthreads();   // all warps finished computing chunk cch-1 -> its stage is free
        if (cch + 1 < NCk) {
            int k0 = (cch + 1) << 6;
            uint32_t base = smb + (uint32_t)(((cch + 1) & 1) * 2 * GSTG) * 2;
            uint32_t sA = base, sB = base + GSTG * 2;
#pragma unroll
            for (int i = 0; i < 4; i++) {
                int idx = tid + i * 256;
                int r = idx >> 3, c = idx & 7;
                uint32_t d = (uint32_t)(r * AST + c * 8) * 2;
                CP_ASYNC16(sA + d, Ap + (size_t)r * K + k0 + c * 8);
                CP_ASYNC16(sB + d, Bp + (size_t)r * K + k0 + c * 8);
            }
            CP_COMMIT();
        }

        uint32_t base = smb + (uint32_t)((cch & 1) * 2 * GSTG) * 2;
        uint32_t sA = base, sB = base + GSTG * 2;
#pragma unroll
        for (int ks = 0; ks < 4; ks++) {
            uint32_t ah[2][4];
#pragma unroll
            for (int mi = 0; mi < 2; mi++)
                ldsm4(ah[mi], sA + (aIdx + mi * 16 * AST + ks * 16) * 2);
#pragma unroll
            for (int njg = 0; njg < 4; njg++) {
                uint32_t bh4[4];
                ldsm4(bh4, sB + (bIdx + njg * 16 * AST + ks * 16) * 2);
#pragma unroll
                for (int mi = 0; mi < 2; mi++) {
                    mma_f16(acc[mi][njg * 2 + 0], ah[mi], bh4 + 0);
                    mma_f16(acc[mi][njg * 2 + 1], ah[mi], bh4 + 2);
                }
            }
        }
    }

    // ---- epilogue ----
    const int g = lane >> 2, tig = lane & 3;
#pragma unroll
    for (int mi = 0; mi < 2; mi++) {
#pragma unroll
        for (int nj = 0; nj < 8; nj++) {
            int ctile = wn * 64 + nj * 8 + tig * 2;
#pragma unroll
            for (int half = 0; half < 2; half++) {
                int m = m0 + wm * 32 + mi * 16 + g + half * 8;
                float v0 = acc[mi][nj][half * 2 + 0];
                float v1 = acc[mi][nj][half * 2 + 1];
                if (MODE == 0) {
                    int which = n0 >> 10;
                    const float* bsel = (which == 0) ? b0 : ((which == 1) ? b1 : b2);
                    __half* Hsel = (which == 0) ? H0 : ((which == 1) ? H1 : H2);
                    float scale = (which == 0) ? 0.125f * 1.44269504f : 1.0f;
                    int nloc = (n0 & 1023) + ctile;
                    int h = nloc >> 6, e = nloc & 63;
                    int bb = m >> 11, s = m & 2047;
                    __half2 w = __floats2half2_rn((v0 + bsel[nloc]) * scale,
                                                  (v1 + bsel[nloc + 1]) * scale);
                    *(__half2*)(Hsel + (((size_t)bb * NH + h) * SEQ + s) * DHD + e) = w;
                } else if (MODE == 1) {
                    int n = n0 + ctile;
                    __half2 w = __floats2half2_rn(fmaxf(v0 + b0[n], 0.f),
                                                  fmaxf(v1 + b0[n + 1], 0.f));
                    *(__half2*)(H0 + (size_t)m * N + n) = w;
                } else {
                    int n = n0 + ctile;
                    // residual-fused: h1 + (acc + bias)  (same addition order as old LN input)
                    float2 rres = *(const float2*)(R0 + (size_t)m * N + n);
                    float2 w = make_float2(rres.x + (v0 + b0[n]),
                                           rres.y + (v1 + b0[n + 1]));
                    *(float2*)(C0 + (size_t)m * N + n) = w;
                }
            }
        }
    }
}

// ================= HMMA fp16 flash attention (single-sync pipeline) =====
#define ATS2 72
#define Q_ELEMS (128*ATS2)
#define STG_ELEMS (64*ATS2)
#define ATT_SMEM_BYTES ((Q_ELEMS + 4*STG_ELEMS) * 2)

__global__ __launch_bounds__(256, 2)
void attn_mma_kernel(const __half* __restrict__ Q, const __half* __restrict__ Kg,
                     const __half* __restrict__ Vg, float* __restrict__ O)
{
    extern __shared__ __align__(16) __half smh[];
    __half* Qh = smh;

    const int tid = threadIdx.x;
    const int wid = tid >> 5, lane = tid & 31;
    const int g = lane >> 2, t = lane & 3;
    const int b = blockIdx.z, h = blockIdx.y;
    const int q0 = blockIdx.x * 128;
    const size_t bh = ((size_t)b * NH + h) * SEQ;
    const __half* qb = Q + (bh + q0) * DHD;

    const uint32_t sQ  = smem_u32(Qh);
    const uint32_t sSt = sQ + Q_ELEMS * 2;

    // prologue: Q + tile 0 in one group
#pragma unroll
    for (int i = 0; i < 4; i++) {
        int idx = tid + i * 256;
        int r = idx >> 3, c = idx & 7;
        CP_ASYNC16(sQ + (uint32_t)(r * ATS2 + c * 8) * 2, qb + r * DHD + c * 8);
    }
    {
        const __half* kb = Kg + bh * DHD;
        const __half* vb = Vg + bh * DHD;
#pragma unroll
        for (int i = 0; i < 2; i++) {
            int idx = tid + i * 256;
            int r = idx >> 3, c = idx & 7;
            uint32_t d = (uint32_t)(r * ATS2 + c * 8) * 2;
            CP_ASYNC16(sSt + d, kb + r * DHD + c * 8);
            CP_ASYNC16(sSt + STG_ELEMS * 2 + d, vb + r * DHD + c * 8);
        }
    }
    CP_COMMIT();

    const uint32_t aIdx = (uint32_t)((wid * 16 + (lane & 15)) * ATS2 + ((lane & 16) ? 8 : 0));
    const uint32_t kIdx = (uint32_t)(((lane & 7) + ((lane & 16) ? 8 : 0)) * ATS2
                                     + ((lane & 8) ? 8 : 0));
    const uint32_t vIdx = (uint32_t)((lane & 15) * ATS2 + ((lane & 16) ? 8 : 0));

    uint32_t qf[4][4];
    float o[8][4];
    float l0p = 0.f, l1p = 0.f;
#pragma unroll
    for (int j = 0; j < 8; j++)
#pragma unroll
        for (int q = 0; q < 4; q++) o[j][q] = 0.f;

    const int NT = SEQ / 64;
    for (int kt = 0; kt < NT; kt++) {
        CP_WAIT(0);
        __syncthreads();
        if (kt + 1 < NT) {
            const __half* kb = Kg + (bh + (size_t)(kt + 1) * 64) * DHD;
            const __half* vb = Vg + (bh + (size_t)(kt + 1) * 64) * DHD;
            uint32_t base = sSt + (uint32_t)(((kt + 1) & 1) * 2 * STG_ELEMS) * 2;
#pragma unroll
            for (int i = 0; i < 2; i++) {
                int idx = tid + i * 256;
                int r = idx >> 3, c = idx & 7;
                uint32_t d = (uint32_t)(r * ATS2 + c * 8) * 2;
                CP_ASYNC16(base + d, kb + r * DHD + c * 8);
                CP_ASYNC16(base + STG_ELEMS * 2 + d, vb + r * DHD + c * 8);
            }
            CP_COMMIT();
        }
        if (kt == 0) {
#pragma unroll
            for (int ks = 0; ks < 4; ks++)
                ldsm4(qf[ks], sQ + (aIdx + ks * 16) * 2);
        }
        const uint32_t sK = sSt + (uint32_t)((kt & 1) * 2 * STG_ELEMS) * 2;
        const uint32_t sV = sK + STG_ELEMS * 2;

        float sc[8][4];
#pragma unroll
        for (int j = 0; j < 8; j++)
#pragma unroll
            for (int q = 0; q < 4; q++) sc[j][q] = 0.f;
#pragma unroll
        for (int ks = 0; ks < 4; ks++) {
#pragma unroll
            for (int njg = 0; njg < 4; njg++) {
                uint32_t bh4[4];
                ldsm4(bh4, sK + (kIdx + njg * 16 * ATS2 + ks * 16) * 2);
                mma_f16(sc[njg * 2 + 0], qf[ks], bh4 + 0);
                mma_f16(sc[njg * 2 + 1], qf[ks], bh4 + 2);
            }
        }

        uint32_t pf[4][4];
#pragma unroll
        for (int ks = 0; ks < 4; ks++) {
            pf[ks][0] = pack_h2(sc[2 * ks][0],     sc[2 * ks][1]);
            pf[ks][1] = pack_h2(sc[2 * ks][2],     sc[2 * ks][3]);
            pf[ks][2] = pack_h2(sc[2 * ks + 1][0], sc[2 * ks + 1][1]);
            pf[ks][3] = pack_h2(sc[2 * ks + 1][2], sc[2 * ks + 1][3]);
#pragma unroll
            for (int i = 0; i < 4; i++)
                asm("ex2.approx.f16x2 %0, %0;" : "+r"(pf[ks][i]));
        }

        {
            __half2 a0 = __float2half2_rn(0.f), a1 = a0;
#pragma unroll
            for (int ks = 0; ks < 4; ks++) {
                a0 = __hadd2(a0, *(__half2*)&pf[ks][0]);
                a0 = __hadd2(a0, *(__half2*)&pf[ks][2]);
                a1 = __hadd2(a1, *(__half2*)&pf[ks][1]);
                a1 = __hadd2(a1, *(__half2*)&pf[ks][3]);
            }
            float2 f0 = __half22float2(a0), f1 = __half22float2(a1);
            l0p += f0.x + f0.y;
            l1p += f1.x + f1.y;
        }

#pragma unroll
        for (int ks = 0; ks < 4; ks++) {
#pragma unroll
            for (int njg = 0; njg < 4; njg++) {
                uint32_t vv[4];
                ldsm4t(vv, sV + (vIdx + ks * 16 * ATS2 + njg * 16) * 2);
                mma_f16(o[njg * 2 + 0], pf[ks], vv + 0);
                mma_f16(o[njg * 2 + 1], pf[ks], vv + 2);
            }
        }
    }

    l0p += __shfl_xor_sync(0xffffffffu, l0p, 1);
    l0p += __shfl_xor_sync(0xffffffffu, l0p, 2);
    l1p += __shfl_xor_sync(0xffffffffu, l1p, 1);
    l1p += __shfl_xor_sync(0xffffffffu, l1p, 2);
    float inv0 = 1.f / l0p, inv1 = 1.f / l1p;
    int row0 = q0 + wid * 16 + g;
#pragma unroll
    for (int j = 0; j < 8; j++) {
        int e = j * 8 + t * 2;
        float* dst0 = O + ((size_t)b * SEQ + row0) * DIM + h * DHD + e;
        float* dst1 = O + ((size_t)b * SEQ + row0 + 8) * DIM + h * DHD + e;
        *(float2*)dst0 = make_float2(o[j][0] * inv0, o[j][1] * inv0);
        *(float2*)dst1 = make_float2(o[j][2] * inv1, o[j][3] * inv1);
    }
}

// ================= add + layernorm (r may be null; optional fp16 copy) =======
__global__ __launch_bounds__(256)
void add_ln_kernel(const float* __restrict__ a, const float* __restrict__ r,
                   const float* __restrict__ gg, const float* __restrict__ bb,
                   float* __restrict__ out, __half* __restrict__ outh)
{
    const int row = blockIdx.x;
    const size_t base = (size_t)row * DIM;
    float v[4];
    float sum = 0.f, sq = 0.f;
#pragma unroll
    for (int k = 0; k < 4; k++) {
        int i = threadIdx.x + k * 256;
        float tv = a[base + i] + (r ? r[base + i] : 0.f);
        v[k] = tv;
        sum += tv;
        sq  += tv * tv;
    }
#pragma unroll
    for (int off = 16; off; off >>= 1) {
        sum += __shfl_xor_sync(0xffffffffu, sum, off);
        sq  += __shfl_xor_sync(0xffffffffu, sq,  off);
    }
    __shared__ float s1[8], s2[8];
    int w = threadIdx.x >> 5, ln = threadIdx.x & 31;
    if (ln == 0) { s1[w] = sum; s2[w] = sq; }
    __syncthreads();
    if (threadIdx.x == 0) {
        float ts = 0.f, tq = 0.f;
#pragma unroll
        for (int i = 0; i < 8; i++) { ts += s1[i]; tq += s2[i]; }
        s1[0] = ts; s2[0] = tq;
    }
    __syncthreads();
    float mean = s1[0] * (1.f / DIM);
    float var  = s2[0] * (1.f / DIM) - mean * mean;
    float rstd = rsqrtf(var + 1e-5f);
#pragma unroll
    for (int k = 0; k < 4; k++) {
        int i = threadIdx.x + k * 256;
        float y = (v[k] - mean) * rstd * gg[i] + bb[i];
        out[base + i] = y;
        if (outh) outh[base + i] = __float2half_rn(y);
    }
}

// ================= launch =================
extern "C" void kernel_launch(void* const* d_in, const int* in_sizes, int n_in,
                              void* d_out, int out_size)
{
    (void)in_sizes; (void)n_in; (void)out_size;
    const float* x  = (const float*)d_in[0];
    const float* Wq = (const float*)d_in[2];
    const float* bq = (const float*)d_in[3];
    const float* Wk = (const float*)d_in[4];
    const float* bk = (const float*)d_in[5];
    const float* Wv = (const float*)d_in[6];
    const float* bv = (const float*)d_in[7];
    const float* lg = (const float*)d_in[8];
    const float* lb = (const float*)d_in[9];
    const float* W1 = (const float*)d_in[10];
    const float* b1 = (const float*)d_in[11];
    const float* W2 = (const float*)d_in[12];
    const float* b2 = (const float*)d_in[13];
    float* out = (float*)d_out;

    float *attp, *h1p, *resp;
    __half *xh, *qp, *kp, *vp, *h1h, *acth;
    cudaGetSymbolAddress((void**)&xh,   g_x_h);
    cudaGetSymbolAddress((void**)&qp,   g_q);
    cudaGetSymbolAddress((void**)&kp,   g_k);
    cudaGetSymbolAddress((void**)&vp,   g_v);
    cudaGetSymbolAddress((void**)&attp, g_att);
    cudaGetSymbolAddress((void**)&h1p,  g_h1);
    cudaGetSymbolAddress((void**)&h1h,  g_h1_h);
    cudaGetSymbolAddress((void**)&acth, g_act_h);
    cudaGetSymbolAddress((void**)&resp, g_res);

    __half *qkvh, *w1h, *w2h;
    cudaGetSymbolAddress((void**)&qkvh, g_qkv_h);
    cudaGetSymbolAddress((void**)&w1h,  g_w1_h);
    cudaGetSymbolAddress((void**)&w2h,  g_w2_h);

    cudaFuncSetAttribute(attn_mma_kernel,
                         cudaFuncAttributeMaxDynamicSharedMemorySize, ATT_SMEM_BYTES);
    cudaFuncSetAttribute(gemm_mma<0>,
                         cudaFuncAttributeMaxDynamicSharedMemorySize, GEMM_SMEM);
    cudaFuncSetAttribute(gemm_mma<1>,
                         cudaFuncAttributeMaxDynamicSharedMemorySize, GEMM_SMEM);
    cudaFuncSetAttribute(gemm_mma<2>,
                         cudaFuncAttributeMaxDynamicSharedMemorySize, GEMM_SMEM);

    dim3 blk(256);

    // 0) preprocess: weights -> fp16 transposed; x -> fp16
    transpose_qkv_kernel<<<dim3(2, 32, 48), blk>>>(Wq, Wk, Wv, qkvh);
    transpose_h_kernel<<<dim3(128, 32, 1), blk>>>(W1, w1h, DIM, DFF, 0, 0);
    transpose_h_kernel<<<dim3(32, 128, 1), blk>>>(W2, w2h, DFF, DIM, 0, 0);
    f2h_kernel<<<(NTOK * DIM) / (256 * 8), blk>>>(x, xh);

    // 1) fused QKV projection -> fp16 q(scaled)/k/v
    gemm_mma<0><<<dim3(NTOK / 128, (3 * DIM) / 128), blk, GEMM_SMEM>>>(
        xh, qkvh, bq, bk, bv, nullptr, nullptr, qp, kp, vp, DIM, 3 * DIM);

    // 2) flash attention -> g_att [B,S,D]
    attn_mma_kernel<<<dim3(SEQ / 128, NH, BN), blk, ATT_SMEM_BYTES>>>(qp, kp, vp, attp);

    // 3) h1 = LN(x + mha), fp32 + fp16 copies
    add_ln_kernel<<<NTOK, blk>>>(x, attp, lg, lb, h1p, h1h);

    // 4) act = relu(h1 @ W1 + b1) -> fp16
    gemm_mma<1><<<dim3(NTOK / 128, DFF / 128), blk, GEMM_SMEM>>>(
        h1h, w1h, b1, nullptr, nullptr, nullptr, nullptr, acth, nullptr, nullptr, DIM, DFF);

    // 5) res = h1 + (act @ W2 + b2)  (residual fused in epilogue)
    gemm_mma<2><<<dim3(NTOK / 128, DIM / 128), blk, GEMM_SMEM>>>(
        acth, w2h, b2, nullptr, nullptr, resp, h1p, nullptr, nullptr, nullptr, DFF, DIM);

    // 6) out = LN(res)
    add_ln_kernel<<<NTOK, blk>>>(resp, nullptr, lg, lb, out, nullptr);
}